// round 5
// baseline (speedup 1.0000x reference)
#include <cuda_runtime.h>
#include <cuda_bf16.h>
#include <cuda_fp16.h>
#include <math.h>
#include <stdint.h>

#define NN 100000
#define EE 1600000
#define HH 128
#define BN_EPS 1e-5f
#define CHUNK 512
#define NCHUNK ((NN + CHUNK - 1) / CHUNK)   // 196

// ---------------- device scratch (no allocations allowed) ----------------
__device__ __align__(16) float g_H[NN * HH];     // current hidden state (fp32, residual)
__device__ __align__(16) __half g_H16[NN * HH];  // fp16 copy for SpMM gathers
__device__ __align__(16) float g_Z[NN * HH];     // pre-BN GEMM output
__device__ __align__(16) float g_AGG[NN * HH];   // SpMM output (fp32)
__device__ __align__(16) int   g_degi[NN];       // in-degree (int)
__device__ __align__(16) int   g_off[NN + 1];    // CSR offsets (by destination)
__device__ __align__(16) int   g_cur[NN];        // scatter cursors
__device__ __align__(16) int2  g_edge[EE];       // CSR: {src, val-bits} per slot
__device__ __align__(16) int   g_csum[NCHUNK];   // chunk sums for scan
__device__ __align__(16) float g_sum[HH];
__device__ __align__(16) float g_sumsq[HH];
// swizzled k-major bf16 weight images (3 weights x 32KB each, hi + lo)
__device__ __align__(16) char g_Whi[3 * 32768];
__device__ __align__(16) char g_Wlo[3 * 32768];

// 256B-row swizzle: XOR 16B-chunk index bits[6:4] with row%8 (bits[10:8])
#define SWZ(b) ((b) ^ ((((b) >> 8) & 7u) << 4))

// smem layout for tc gemm (bytes)
#define GS_AHI   0
#define GS_ALO   32768
#define GS_BHI   65536
#define GS_BLO   98304
#define GS_STAT  131072          // 128 sums + 128 ssq (floats)
#define GS_TOTAL (131072 + 1024)

// ---------------- ptx helpers ----------------
__device__ __forceinline__ uint32_t smem_u32(const void* p) {
    uint32_t a;
    asm("{ .reg .u64 t; cvta.to.shared.u64 t, %1; cvt.u32.u64 %0, t; }" : "=r"(a) : "l"(p));
    return a;
}
__device__ __forceinline__ void ldsm_x4(uint32_t* r, uint32_t addr) {
    asm volatile("ldmatrix.sync.aligned.m8n8.x4.shared.b16 {%0,%1,%2,%3}, [%4];"
                 : "=r"(r[0]), "=r"(r[1]), "=r"(r[2]), "=r"(r[3]) : "r"(addr));
}
__device__ __forceinline__ void ldsm_x4_t(uint32_t* r, uint32_t addr) {
    asm volatile("ldmatrix.sync.aligned.m8n8.x4.trans.shared.b16 {%0,%1,%2,%3}, [%4];"
                 : "=r"(r[0]), "=r"(r[1]), "=r"(r[2]), "=r"(r[3]) : "r"(addr));
}
__device__ __forceinline__ void mma16816(float* d, const uint32_t* a, const uint32_t* b) {
    asm volatile("mma.sync.aligned.m16n8k16.row.col.f32.bf16.bf16.f32 "
                 "{%0,%1,%2,%3}, {%4,%5,%6,%7}, {%8,%9}, {%0,%1,%2,%3};"
                 : "+f"(d[0]), "+f"(d[1]), "+f"(d[2]), "+f"(d[3])
                 : "r"(a[0]), "r"(a[1]), "r"(a[2]), "r"(a[3]), "r"(b[0]), "r"(b[1]));
}

// ---------------- utility kernels ----------------
__global__ void zero_int(int* p, int n) {
    int i = blockIdx.x * blockDim.x + threadIdx.x;
    int stride = gridDim.x * blockDim.x;
    for (; i < n; i += stride) p[i] = 0;
}

__global__ void degree_kernel(const int* __restrict__ col) {
    int e = blockIdx.x * blockDim.x + threadIdx.x;
    if (e < EE) atomicAdd(&g_degi[col[e]], 1);
}

// ---------------- CSR build: two-level exclusive scan ----------------
__global__ void chunk_sums_kernel() {
    __shared__ int sh[CHUNK];
    int t = threadIdx.x;
    int n = blockIdx.x * CHUNK + t;
    sh[t] = (n < NN) ? g_degi[n] : 0;
    __syncthreads();
    for (int s = CHUNK / 2; s > 0; s >>= 1) {
        if (t < s) sh[t] += sh[t + s];
        __syncthreads();
    }
    if (t == 0) g_csum[blockIdx.x] = sh[0];
}

__global__ void scan_csum_kernel() {   // 1 block, 256 threads, exclusive scan of NCHUNK
    __shared__ int sh[256];
    int t = threadIdx.x;
    int v = (t < NCHUNK) ? g_csum[t] : 0;
    sh[t] = v;
    __syncthreads();
    for (int s = 1; s < 256; s <<= 1) {
        int a = (t >= s) ? sh[t - s] : 0;
        __syncthreads();
        sh[t] += a;
        __syncthreads();
    }
    if (t < NCHUNK) g_csum[t] = sh[t] - v;
}

__global__ void scan_offsets_kernel() {
    __shared__ int sh[CHUNK];
    int t = threadIdx.x;
    int n = blockIdx.x * CHUNK + t;
    int v = (n < NN) ? g_degi[n] : 0;
    sh[t] = v;
    __syncthreads();
    for (int s = 1; s < CHUNK; s <<= 1) {
        int add = (t >= s) ? sh[t - s] : 0;
        __syncthreads();
        sh[t] += add;
        __syncthreads();
    }
    int excl = sh[t] - v + g_csum[blockIdx.x];
    if (n < NN) { g_off[n] = excl; g_cur[n] = excl; }
    if (n == NN - 1) g_off[NN] = excl + v;   // == EE
}

__global__ void val_scatter_kernel(const int* __restrict__ row, const int* __restrict__ col,
                                   const float* __restrict__ w) {
    int e = blockIdx.x * blockDim.x + threadIdx.x;
    if (e < EE) {
        int r = row[e], c = col[e];
        float v = w[e] * rsqrtf((float)g_degi[c]) * rsqrtf((float)g_degi[r]);
        if (!isfinite(v)) v = 0.f;   // nan_to_num
        int p = atomicAdd(&g_cur[c], 1);
        g_edge[p] = make_int2(r, __float_as_int(v));
    }
}

// ---------------- weight conversion (+ BN-stats zeroing for the fc GEMM) ----------------
__global__ void wconvert_kernel(const float* __restrict__ fc_w, const float* __restrict__ conv_w) {
    int idx = blockIdx.x * blockDim.x + threadIdx.x;
    if (blockIdx.x == 0 && threadIdx.x < HH) {
        g_sum[threadIdx.x] = 0.f;
        g_sumsq[threadIdx.x] = 0.f;
    }
    if (idx >= 3 * 16384) return;
    int w   = idx >> 14;
    int rem = idx & 16383;
    int k = rem >> 7;      // input index (row)
    int n = rem & 127;     // output index (col)
    float v = (w == 0) ? fc_w[rem] : conv_w[(w - 1) * 16384 + rem];
    __nv_bfloat16 hi = __float2bfloat16_rn(v);
    __nv_bfloat16 lo = __float2bfloat16_rn(v - __bfloat162float(hi));
    uint32_t byte = (uint32_t)k * 256u + (uint32_t)n * 2u;
    uint32_t sw = SWZ(byte);
    *(__nv_bfloat16*)(g_Whi + (size_t)w * 32768 + sw) = hi;
    *(__nv_bfloat16*)(g_Wlo + (size_t)w * 32768 + sw) = lo;
}

// ---------------- SpMM (CSR by destination, fp16 gathers): one warp per node ----------------
// Block 0 also zeroes the BN stats for the following GEMM.
__global__ __launch_bounds__(256) void spmm_h16_kernel() {
    if (blockIdx.x == 0 && threadIdx.x < HH) {
        g_sum[threadIdx.x] = 0.f;
        g_sumsq[threadIdx.x] = 0.f;
    }
    int warp = (blockIdx.x * blockDim.x + threadIdx.x) >> 5;
    int lane = threadIdx.x & 31;
    if (warp >= NN) return;
    int s = g_off[warp];
    int e = g_off[warp + 1];
    const uint2* H2 = reinterpret_cast<const uint2*>(g_H16);   // 8B = 4 halves per lane
    float acc0 = 0.f, acc1 = 0.f, acc2 = 0.f, acc3 = 0.f;
    int k = s;
    for (; k + 3 < e; k += 4) {
        int2 e0 = g_edge[k],     e1 = g_edge[k + 1];
        int2 e2 = g_edge[k + 2], e3 = g_edge[k + 3];
        uint2 u0 = H2[(size_t)e0.x * 32 + lane];
        uint2 u1 = H2[(size_t)e1.x * 32 + lane];
        uint2 u2 = H2[(size_t)e2.x * 32 + lane];
        uint2 u3 = H2[(size_t)e3.x * 32 + lane];
        float v0 = __int_as_float(e0.y), v1 = __int_as_float(e1.y);
        float v2 = __int_as_float(e2.y), v3 = __int_as_float(e3.y);
        float2 a, b;
        a = __half22float2(*reinterpret_cast<__half2*>(&u0.x));
        b = __half22float2(*reinterpret_cast<__half2*>(&u0.y));
        acc0 += v0 * a.x; acc1 += v0 * a.y; acc2 += v0 * b.x; acc3 += v0 * b.y;
        a = __half22float2(*reinterpret_cast<__half2*>(&u1.x));
        b = __half22float2(*reinterpret_cast<__half2*>(&u1.y));
        acc0 += v1 * a.x; acc1 += v1 * a.y; acc2 += v1 * b.x; acc3 += v1 * b.y;
        a = __half22float2(*reinterpret_cast<__half2*>(&u2.x));
        b = __half22float2(*reinterpret_cast<__half2*>(&u2.y));
        acc0 += v2 * a.x; acc1 += v2 * a.y; acc2 += v2 * b.x; acc3 += v2 * b.y;
        a = __half22float2(*reinterpret_cast<__half2*>(&u3.x));
        b = __half22float2(*reinterpret_cast<__half2*>(&u3.y));
        acc0 += v3 * a.x; acc1 += v3 * a.y; acc2 += v3 * b.x; acc3 += v3 * b.y;
    }
    for (; k < e; k++) {
        int2 e0 = g_edge[k];
        uint2 u0 = H2[(size_t)e0.x * 32 + lane];
        float v0 = __int_as_float(e0.y);
        float2 a = __half22float2(*reinterpret_cast<__half2*>(&u0.x));
        float2 b = __half22float2(*reinterpret_cast<__half2*>(&u0.y));
        acc0 += v0 * a.x; acc1 += v0 * a.y; acc2 += v0 * b.x; acc3 += v0 * b.y;
    }
    reinterpret_cast<float4*>(g_AGG)[(size_t)warp * 32 + lane] =
        make_float4(acc0, acc1, acc2, acc3);
}

// ---------------- mma.sync GEMM: C[M,128] = A[M,128] @ W + bias (3xBF16, fp32 acc) ----------------
// Fused BN-stats epilogue into g_sum/g_sumsq.
__global__ __launch_bounds__(256, 1) void gemm_mma_kernel(
    const float* __restrict__ A,
    const char* __restrict__ Whi,   // swizzled 32KB image
    const char* __restrict__ Wlo,
    const float* __restrict__ bias,
    float* __restrict__ C, int M)
{
    extern __shared__ __align__(1024) char smem[];
    uint32_t sb = smem_u32(smem);
    const int tid  = threadIdx.x;
    const int wid  = tid >> 5;
    const int lane = tid & 31;
    const int row0 = blockIdx.x * 128;

    float* s_stat = reinterpret_cast<float*>(smem + GS_STAT);
    s_stat[tid] = 0.f;    // 256 floats: [0:128) sums, [128:256) ssq

    // copy weight images into smem (32KB each = 2048 uint4)
    {
        const uint4* wh = reinterpret_cast<const uint4*>(Whi);
        const uint4* wl = reinterpret_cast<const uint4*>(Wlo);
        uint4* sh = reinterpret_cast<uint4*>(smem + GS_BHI);
        uint4* sl = reinterpret_cast<uint4*>(smem + GS_BLO);
        #pragma unroll
        for (int i = 0; i < 8; i++) {
            sh[tid + i * 256] = wh[tid + i * 256];
            sl[tid + i * 256] = wl[tid + i * 256];
        }
    }

    // load A tile (128 x 128 fp32), split hi/lo bf16, store swizzled k-major
    {
        const float4* A4 = reinterpret_cast<const float4*>(A);
        #pragma unroll
        for (int i = 0; i < 16; i++) {
            int idx = tid + i * 256;
            int m  = idx >> 5;        // 0..127
            int kg = idx & 31;        // float4 group
            int gr = row0 + m;
            float4 a = (gr < M) ? A4[(size_t)gr * 32 + kg] : make_float4(0.f, 0.f, 0.f, 0.f);
            __nv_bfloat16 h0 = __float2bfloat16_rn(a.x);
            __nv_bfloat16 h1 = __float2bfloat16_rn(a.y);
            __nv_bfloat16 h2 = __float2bfloat16_rn(a.z);
            __nv_bfloat16 h3 = __float2bfloat16_rn(a.w);
            __nv_bfloat16 l0 = __float2bfloat16_rn(a.x - __bfloat162float(h0));
            __nv_bfloat16 l1 = __float2bfloat16_rn(a.y - __bfloat162float(h1));
            __nv_bfloat16 l2 = __float2bfloat16_rn(a.z - __bfloat162float(h2));
            __nv_bfloat16 l3 = __float2bfloat16_rn(a.w - __bfloat162float(h3));
            uint32_t byte = (uint32_t)m * 256u + (uint32_t)kg * 8u;
            uint32_t sw = SWZ(byte);
            *reinterpret_cast<__nv_bfloat162*>(smem + GS_AHI + sw)     = __halves2bfloat162(h0, h1);
            *reinterpret_cast<__nv_bfloat162*>(smem + GS_AHI + sw + 4) = __halves2bfloat162(h2, h3);
            *reinterpret_cast<__nv_bfloat162*>(smem + GS_ALO + sw)     = __halves2bfloat162(l0, l1);
            *reinterpret_cast<__nv_bfloat162*>(smem + GS_ALO + sw + 4) = __halves2bfloat162(l2, l3);
        }
    }
    __syncthreads();

    // per-lane ldmatrix address components
    const uint32_t a_m  = (uint32_t)(wid * 16) + (lane & 7) + ((lane >> 3) & 1) * 8;
    const uint32_t a_ks = (uint32_t)(lane >> 4) * 8;
    const uint32_t b_ks = (uint32_t)(lane & 7) + ((lane >> 3) & 1) * 8;
    const uint32_t b_ns = (uint32_t)((lane >> 4) & 1) * 8;

    float acc[64];
    #pragma unroll
    for (int i = 0; i < 64; i++) acc[i] = 0.f;

    const uint32_t abase[3] = { sb + GS_AHI, sb + GS_AHI, sb + GS_ALO };
    const uint32_t bbase[3] = { sb + GS_BHI, sb + GS_BLO, sb + GS_BHI };

    #pragma unroll
    for (int p = 0; p < 3; p++) {
        #pragma unroll
        for (int kc = 0; kc < 8; kc++) {
            uint32_t afrag[4];
            uint32_t ab = a_m * 256u + (kc * 16u + a_ks) * 2u;
            ldsm_x4(afrag, abase[p] + SWZ(ab));
            #pragma unroll
            for (int np = 0; np < 8; np++) {
                uint32_t bfrag[4];
                uint32_t bb = (kc * 16u + b_ks) * 256u + (np * 16u + b_ns) * 2u;
                ldsm_x4_t(bfrag, bbase[p] + SWZ(bb));
                mma16816(&acc[(2 * np) * 4],     afrag, &bfrag[0]);
                mma16816(&acc[(2 * np + 1) * 4], afrag, &bfrag[2]);
            }
        }
    }

    // epilogue: bias add, store, fused BN stats
    int r0 = row0 + wid * 16 + (lane >> 2);
    int r1 = r0 + 8;
    bool v0 = r0 < M, v1 = r1 < M;
    int cb = (lane & 3) * 2;

    #pragma unroll
    for (int nt = 0; nt < 16; nt++) {
        int c = nt * 8 + cb;
        float b0 = __ldg(&bias[c]);
        float b1 = __ldg(&bias[c + 1]);
        float o00 = acc[nt * 4 + 0] + b0;
        float o01 = acc[nt * 4 + 1] + b1;
        float o10 = acc[nt * 4 + 2] + b0;
        float o11 = acc[nt * 4 + 3] + b1;
        if (v0) *reinterpret_cast<float2*>(&C[(size_t)r0 * 128 + c]) = make_float2(o00, o01);
        if (v1) *reinterpret_cast<float2*>(&C[(size_t)r1 * 128 + c]) = make_float2(o10, o11);

        float s0 = (v0 ? o00 : 0.f) + (v1 ? o10 : 0.f);
        float s1 = (v0 ? o01 : 0.f) + (v1 ? o11 : 0.f);
        float q0 = (v0 ? o00 * o00 : 0.f) + (v1 ? o10 * o10 : 0.f);
        float q1 = (v0 ? o01 * o01 : 0.f) + (v1 ? o11 * o11 : 0.f);
        #pragma unroll
        for (int m = 4; m <= 16; m <<= 1) {
            s0 += __shfl_xor_sync(0xFFFFFFFFu, s0, m);
            s1 += __shfl_xor_sync(0xFFFFFFFFu, s1, m);
            q0 += __shfl_xor_sync(0xFFFFFFFFu, q0, m);
            q1 += __shfl_xor_sync(0xFFFFFFFFu, q1, m);
        }
        if (lane < 4) {
            atomicAdd(&s_stat[c], s0);
            atomicAdd(&s_stat[c + 1], s1);
            atomicAdd(&s_stat[128 + c], q0);
            atomicAdd(&s_stat[128 + c + 1], q1);
        }
    }
    __syncthreads();
    if (tid < 128) {
        atomicAdd(&g_sum[tid],   s_stat[tid]);
        atomicAdd(&g_sumsq[tid], s_stat[128 + tid]);
    }
}

// ---------------- BN apply + ReLU (+ optional residual), writes fp32 + optional fp16 ----------------
__global__ void bn_apply_kernel(const float* __restrict__ z,
                                const float* __restrict__ gamma,
                                const float* __restrict__ beta,
                                const float* __restrict__ res,  // may be null
                                float* __restrict__ out,
                                __half* __restrict__ out16)     // may be null
{
    const float inv_n = 1.0f / (float)NN;
    int i = blockIdx.x * blockDim.x + threadIdx.x;
    int stride = gridDim.x * blockDim.x;
    const int n4 = NN * (HH / 4);
    for (; i < n4; i += stride) {
        int c0 = (i & 31) * 4;
        float4 zv = reinterpret_cast<const float4*>(z)[i];
        float o[4] = {zv.x, zv.y, zv.z, zv.w};
        #pragma unroll
        for (int j = 0; j < 4; j++) {
            int c = c0 + j;
            float m  = g_sum[c] * inv_n;
            float vr = g_sumsq[c] * inv_n - m * m;
            float rs = rsqrtf(vr + BN_EPS);
            float y = (o[j] - m) * rs * gamma[c] + beta[c];
            o[j] = fmaxf(y, 0.f);
        }
        float4 ov = make_float4(o[0], o[1], o[2], o[3]);
        if (res != nullptr) {
            float4 rv = reinterpret_cast<const float4*>(res)[i];
            ov.x += rv.x; ov.y += rv.y; ov.z += rv.z; ov.w += rv.w;
        }
        reinterpret_cast<float4*>(out)[i] = ov;
        if (out16 != nullptr) {
            uint2 u;
            *reinterpret_cast<__half2*>(&u.x) = __floats2half2_rn(ov.x, ov.y);
            *reinterpret_cast<__half2*>(&u.y) = __floats2half2_rn(ov.z, ov.w);
            reinterpret_cast<uint2*>(out16)[i] = u;
        }
    }
}

// ---------------- launch ----------------
extern "C" void kernel_launch(void* const* d_in, const int* in_sizes, int n_in,
                              void* d_out, int out_size)
{
    const float* x      = (const float*)d_in[0];
    const int*   ei     = (const int*)  d_in[1];
    const float* ew     = (const float*)d_in[2];
    const float* fc_w   = (const float*)d_in[3];
    const float* fc_b   = (const float*)d_in[4];
    const float* conv_w = (const float*)d_in[5];
    const float* conv_b = (const float*)d_in[6];
    const float* gamma  = (const float*)d_in[7];
    const float* beta   = (const float*)d_in[8];
    float* out = (float*)d_out;

    const int* row = ei;
    const int* col = ei + EE;

    void *pH, *pH16, *pZ, *pAGG, *pDegi, *pWhi, *pWlo;
    cudaGetSymbolAddress(&pH, g_H);
    cudaGetSymbolAddress(&pH16, g_H16);
    cudaGetSymbolAddress(&pZ, g_Z);
    cudaGetSymbolAddress(&pAGG, g_AGG);
    cudaGetSymbolAddress(&pDegi, g_degi);
    cudaGetSymbolAddress(&pWhi, g_Whi);
    cudaGetSymbolAddress(&pWlo, g_Wlo);
    float*  H   = (float*)pH;
    __half* H16 = (__half*)pH16;
    float*  Z   = (float*)pZ;
    float*  AGG = (float*)pAGG;
    const char* Whi = (const char*)pWhi;
    const char* Wlo = (const char*)pWlo;

    static int smem_set = 0;
    if (!smem_set) {
        cudaFuncSetAttribute(gemm_mma_kernel, cudaFuncAttributeMaxDynamicSharedMemorySize, GS_TOTAL);
        smem_set = 1;
    }

    const int egrid = (EE + 255) / 256;
    const int ggrid = (NN + 127) / 128;   // 782

    // launches 1-3: degree + weight conversion (stats zeroed inside wconvert)
    zero_int<<<128, 256>>>((int*)pDegi, NN);
    degree_kernel<<<egrid, 256>>>(col);
    wconvert_kernel<<<(3 * 16384 + 255) / 256, 256>>>(fc_w, conv_w);

    // launch 4 (profiled): fc GEMM
    gemm_mma_kernel<<<ggrid, 256, GS_TOTAL>>>(x, Whi, Wlo, fc_b, Z, NN);

    // CSR build (independent of the fc GEMM)
    chunk_sums_kernel<<<NCHUNK, CHUNK>>>();
    scan_csum_kernel<<<1, 256>>>();
    scan_offsets_kernel<<<NCHUNK, CHUNK>>>();
    val_scatter_kernel<<<egrid, 256>>>(row, col, ew);

    // fc BN + ReLU
    bn_apply_kernel<<<4096, 256>>>(Z, gamma, beta, nullptr, H, H16);

    for (int l = 0; l < 2; l++) {
        spmm_h16_kernel<<<(NN * 32 + 255) / 256, 256>>>();   // also zeroes BN stats
        gemm_mma_kernel<<<ggrid, 256, GS_TOTAL>>>(AGG, Whi + (size_t)(l + 1) * 32768,
                                                  Wlo + (size_t)(l + 1) * 32768,
                                                  conv_b + l * HH, Z, NN);
        bn_apply_kernel<<<4096, 256>>>(Z, gamma + (l + 1) * HH, beta + (l + 1) * HH,
                                       H, (l == 1) ? out : H, (l == 1) ? nullptr : H16);
    }
}

// round 6
// speedup vs baseline: 1.2393x; 1.2393x over previous
#include <cuda_runtime.h>
#include <cuda_bf16.h>
#include <math.h>
#include <stdint.h>

#define NN 100000
#define EE 1600000
#define HH 128
#define BN_EPS 1e-5f
#define CHUNK 512
#define NCHUNK ((NN + CHUNK - 1) / CHUNK)   // 196

// ---------------- device scratch (no allocations allowed) ----------------
__device__ __align__(16) float g_H[NN * HH];     // current hidden state
__device__ __align__(16) float g_Z[NN * HH];     // pre-BN GEMM output
__device__ __align__(16) float g_AGG[NN * HH];   // SpMM output
__device__ __align__(16) int   g_degi[NN];       // in-degree (int)
__device__ __align__(16) int   g_off[NN + 1];    // CSR offsets (by destination)
__device__ __align__(16) int   g_cur[NN];        // scatter cursors
__device__ __align__(16) int2  g_edge[EE];       // CSR: {src, val-bits} per slot
__device__ __align__(16) int   g_csum[NCHUNK];   // chunk sums for scan
__device__ __align__(16) float g_sum[HH];
__device__ __align__(16) float g_sumsq[HH];
// swizzled k-major bf16 weight images (3 weights x 32KB each, hi + lo)
__device__ __align__(16) char g_Whi[3 * 32768];
__device__ __align__(16) char g_Wlo[3 * 32768];

// 256B-row swizzle: XOR 16B-chunk index bits[6:4] with row%8 (bits[10:8])
#define SWZ(b) ((b) ^ ((((b) >> 8) & 7u) << 4))

// persistent-gemm smem layout (bytes)
#define PS_RAW   0            // 64KB raw fp32 A tile (cp.async staging)
#define PS_AHI   65536        // 32KB
#define PS_ALO   98304        // 32KB
#define PS_BHI   131072       // 32KB
#define PS_BLO   163840       // 32KB
#define PS_STAT  196608       // 256 floats
#define PS_TOTAL (196608 + 1024)

// ---------------- ptx helpers ----------------
__device__ __forceinline__ uint32_t smem_u32(const void* p) {
    uint32_t a;
    asm("{ .reg .u64 t; cvta.to.shared.u64 t, %1; cvt.u32.u64 %0, t; }" : "=r"(a) : "l"(p));
    return a;
}
__device__ __forceinline__ void ldsm_x4(uint32_t* r, uint32_t addr) {
    asm volatile("ldmatrix.sync.aligned.m8n8.x4.shared.b16 {%0,%1,%2,%3}, [%4];"
                 : "=r"(r[0]), "=r"(r[1]), "=r"(r[2]), "=r"(r[3]) : "r"(addr));
}
__device__ __forceinline__ void ldsm_x4_t(uint32_t* r, uint32_t addr) {
    asm volatile("ldmatrix.sync.aligned.m8n8.x4.trans.shared.b16 {%0,%1,%2,%3}, [%4];"
                 : "=r"(r[0]), "=r"(r[1]), "=r"(r[2]), "=r"(r[3]) : "r"(addr));
}
__device__ __forceinline__ void mma16816(float* d, const uint32_t* a, const uint32_t* b) {
    asm volatile("mma.sync.aligned.m16n8k16.row.col.f32.bf16.bf16.f32 "
                 "{%0,%1,%2,%3}, {%4,%5,%6,%7}, {%8,%9}, {%0,%1,%2,%3};"
                 : "+f"(d[0]), "+f"(d[1]), "+f"(d[2]), "+f"(d[3])
                 : "r"(a[0]), "r"(a[1]), "r"(a[2]), "r"(a[3]), "r"(b[0]), "r"(b[1]));
}
__device__ __forceinline__ void cp_async16(uint32_t dst, const void* src, int sz) {
    asm volatile("cp.async.cg.shared.global [%0], [%1], 16, %2;"
                 :: "r"(dst), "l"(src), "r"(sz) : "memory");
}
__device__ __forceinline__ void cp_commit() {
    asm volatile("cp.async.commit_group;" ::: "memory");
}
__device__ __forceinline__ void cp_wait0() {
    asm volatile("cp.async.wait_group 0;" ::: "memory");
}

// ---------------- utility kernels ----------------
__global__ void zero_int(int* p, int n) {
    int i = blockIdx.x * blockDim.x + threadIdx.x;
    int stride = gridDim.x * blockDim.x;
    for (; i < n; i += stride) p[i] = 0;
}

__global__ void degree_kernel(const int* __restrict__ col) {
    int e = blockIdx.x * blockDim.x + threadIdx.x;
    if (e < EE) atomicAdd(&g_degi[col[e]], 1);
}

// ---------------- CSR build: two-level exclusive scan ----------------
__global__ void chunk_sums_kernel() {
    __shared__ int sh[CHUNK];
    int t = threadIdx.x;
    int n = blockIdx.x * CHUNK + t;
    sh[t] = (n < NN) ? g_degi[n] : 0;
    __syncthreads();
    for (int s = CHUNK / 2; s > 0; s >>= 1) {
        if (t < s) sh[t] += sh[t + s];
        __syncthreads();
    }
    if (t == 0) g_csum[blockIdx.x] = sh[0];
}

__global__ void scan_csum_kernel() {   // 1 block, 256 threads
    __shared__ int sh[256];
    int t = threadIdx.x;
    int v = (t < NCHUNK) ? g_csum[t] : 0;
    sh[t] = v;
    __syncthreads();
    for (int s = 1; s < 256; s <<= 1) {
        int a = (t >= s) ? sh[t - s] : 0;
        __syncthreads();
        sh[t] += a;
        __syncthreads();
    }
    if (t < NCHUNK) g_csum[t] = sh[t] - v;
}

__global__ void scan_offsets_kernel() {
    __shared__ int sh[CHUNK];
    int t = threadIdx.x;
    int n = blockIdx.x * CHUNK + t;
    int v = (n < NN) ? g_degi[n] : 0;
    sh[t] = v;
    __syncthreads();
    for (int s = 1; s < CHUNK; s <<= 1) {
        int add = (t >= s) ? sh[t - s] : 0;
        __syncthreads();
        sh[t] += add;
        __syncthreads();
    }
    int excl = sh[t] - v + g_csum[blockIdx.x];
    if (n < NN) { g_off[n] = excl; g_cur[n] = excl; }
    if (n == NN - 1) g_off[NN] = excl + v;   // == EE
}

__global__ void val_scatter_kernel(const int* __restrict__ row, const int* __restrict__ col,
                                   const float* __restrict__ w) {
    int e = blockIdx.x * blockDim.x + threadIdx.x;
    if (e < EE) {
        int r = row[e], c = col[e];
        float v = w[e] * rsqrtf((float)g_degi[c]) * rsqrtf((float)g_degi[r]);
        if (!isfinite(v)) v = 0.f;   // nan_to_num
        int p = atomicAdd(&g_cur[c], 1);
        g_edge[p] = make_int2(r, __float_as_int(v));
    }
}

// ---------------- weight conversion (+ BN-stats zeroing for the fc GEMM) ----------------
__global__ void wconvert_kernel(const float* __restrict__ fc_w, const float* __restrict__ conv_w) {
    int idx = blockIdx.x * blockDim.x + threadIdx.x;
    if (blockIdx.x == 0 && threadIdx.x < HH) {
        g_sum[threadIdx.x] = 0.f;
        g_sumsq[threadIdx.x] = 0.f;
    }
    if (idx >= 3 * 16384) return;
    int w   = idx >> 14;
    int rem = idx & 16383;
    int k = rem >> 7;      // input index (row)
    int n = rem & 127;     // output index (col)
    float v = (w == 0) ? fc_w[rem] : conv_w[(w - 1) * 16384 + rem];
    __nv_bfloat16 hi = __float2bfloat16_rn(v);
    __nv_bfloat16 lo = __float2bfloat16_rn(v - __bfloat162float(hi));
    uint32_t byte = (uint32_t)k * 256u + (uint32_t)n * 2u;
    uint32_t sw = SWZ(byte);
    *(__nv_bfloat16*)(g_Whi + (size_t)w * 32768 + sw) = hi;
    *(__nv_bfloat16*)(g_Wlo + (size_t)w * 32768 + sw) = lo;
}

// ---------------- SpMM (CSR by destination, fp32): one warp per node ----------------
// Block 0 also zeroes the BN stats for the following GEMM.
__global__ __launch_bounds__(256) void spmm_csr_kernel() {
    if (blockIdx.x == 0 && threadIdx.x < HH) {
        g_sum[threadIdx.x] = 0.f;
        g_sumsq[threadIdx.x] = 0.f;
    }
    int warp = (blockIdx.x * blockDim.x + threadIdx.x) >> 5;
    int lane = threadIdx.x & 31;
    if (warp >= NN) return;
    int s = g_off[warp];
    int e = g_off[warp + 1];
    const float4* H4 = reinterpret_cast<const float4*>(g_H);
    float4 acc = make_float4(0.f, 0.f, 0.f, 0.f);
    int k = s;
    for (; k + 1 < e; k += 2) {
        int2 e0 = g_edge[k], e1 = g_edge[k + 1];
        float v0 = __int_as_float(e0.y), v1 = __int_as_float(e1.y);
        float4 a = H4[(size_t)e0.x * 32 + lane];
        float4 b = H4[(size_t)e1.x * 32 + lane];
        acc.x += v0 * a.x + v1 * b.x;
        acc.y += v0 * a.y + v1 * b.y;
        acc.z += v0 * a.z + v1 * b.z;
        acc.w += v0 * a.w + v1 * b.w;
    }
    if (k < e) {
        int2 e0 = g_edge[k];
        float v0 = __int_as_float(e0.y);
        float4 a = H4[(size_t)e0.x * 32 + lane];
        acc.x += v0 * a.x; acc.y += v0 * a.y;
        acc.z += v0 * a.z; acc.w += v0 * a.w;
    }
    reinterpret_cast<float4*>(g_AGG)[(size_t)warp * 32 + lane] = acc;
}

// ---------------- persistent pipelined mma GEMM: C = A @ W + bias, fused BN stats ----------------
__device__ __forceinline__ void stage_A_tile(uint32_t sb, const float* __restrict__ A,
                                             int tile, int M, int tid) {
    int row0 = tile * 128;
    #pragma unroll
    for (int i = 0; i < 16; i++) {
        int idx = tid + i * 256;          // 0..4095
        int m  = idx >> 5;
        int kg = idx & 31;
        int gr = row0 + m;
        uint32_t dst = sb + PS_RAW + (uint32_t)idx * 16u;
        const float* src = A + (size_t)gr * 128 + kg * 4;
        int sz = (gr < M) ? 16 : 0;       // zero-fill OOB rows
        cp_async16(dst, src, sz);
    }
    cp_commit();
}

__global__ __launch_bounds__(256, 1) void gemm_persist_kernel(
    const float* __restrict__ A,
    const char* __restrict__ Whi,   // swizzled 32KB image
    const char* __restrict__ Wlo,
    const float* __restrict__ bias,
    float* __restrict__ C, int M)
{
    extern __shared__ __align__(1024) char smem[];
    uint32_t sb = smem_u32(smem);
    const int tid  = threadIdx.x;
    const int wid  = tid >> 5;
    const int lane = tid & 31;
    const int NT   = (M + 127) >> 7;

    float* s_stat = reinterpret_cast<float*>(smem + PS_STAT);
    s_stat[tid] = 0.f;    // 256 floats: [0:128) sums, [128:256) ssq

    // prologue: weights into smem + first A tile, all via cp.async
    #pragma unroll
    for (int i = 0; i < 8; i++) {
        uint32_t off = (uint32_t)(tid + i * 256) * 16u;
        cp_async16(sb + PS_BHI + off, Whi + off, 16);
        cp_async16(sb + PS_BLO + off, Wlo + off, 16);
    }
    int tile = blockIdx.x;
    if (tile < NT) stage_A_tile(sb, A, tile, M, tid);
    cp_wait0();
    __syncthreads();

    // per-lane ldmatrix address components
    const uint32_t a_m  = (uint32_t)(wid * 16) + (lane & 7) + ((lane >> 3) & 1) * 8;
    const uint32_t a_ks = (uint32_t)(lane >> 4) * 8;
    const uint32_t b_ks = (uint32_t)(lane & 7) + ((lane >> 3) & 1) * 8;
    const uint32_t b_ns = (uint32_t)((lane >> 4) & 1) * 8;

    const uint32_t abase[3] = { sb + PS_AHI, sb + PS_AHI, sb + PS_ALO };
    const uint32_t bbase[3] = { sb + PS_BHI, sb + PS_BLO, sb + PS_BHI };

    for (; tile < NT; tile += gridDim.x) {
        // convert raw fp32 A -> hi/lo bf16 swizzled images
        #pragma unroll
        for (int i = 0; i < 16; i++) {
            int idx = tid + i * 256;
            int m  = idx >> 5;
            int kg = idx & 31;
            float4 a = *reinterpret_cast<const float4*>(smem + PS_RAW + (uint32_t)idx * 16u);
            __nv_bfloat16 h0 = __float2bfloat16_rn(a.x);
            __nv_bfloat16 h1 = __float2bfloat16_rn(a.y);
            __nv_bfloat16 h2 = __float2bfloat16_rn(a.z);
            __nv_bfloat16 h3 = __float2bfloat16_rn(a.w);
            __nv_bfloat16 l0 = __float2bfloat16_rn(a.x - __bfloat162float(h0));
            __nv_bfloat16 l1 = __float2bfloat16_rn(a.y - __bfloat162float(h1));
            __nv_bfloat16 l2 = __float2bfloat16_rn(a.z - __bfloat162float(h2));
            __nv_bfloat16 l3 = __float2bfloat16_rn(a.w - __bfloat162float(h3));
            uint32_t sw = SWZ((uint32_t)m * 256u + (uint32_t)kg * 8u);
            *reinterpret_cast<__nv_bfloat162*>(smem + PS_AHI + sw)     = __halves2bfloat162(h0, h1);
            *reinterpret_cast<__nv_bfloat162*>(smem + PS_AHI + sw + 4) = __halves2bfloat162(h2, h3);
            *reinterpret_cast<__nv_bfloat162*>(smem + PS_ALO + sw)     = __halves2bfloat162(l0, l1);
            *reinterpret_cast<__nv_bfloat162*>(smem + PS_ALO + sw + 4) = __halves2bfloat162(l2, l3);
        }
        __syncthreads();   // raw buffer free; hi/lo images ready

        // prefetch next tile's raw A (overlaps with MMA below)
        int ntile = tile + gridDim.x;
        if (ntile < NT) stage_A_tile(sb, A, ntile, M, tid);

        // MMA: 3 passes x 8 k-chunks
        float acc[64];
        #pragma unroll
        for (int i = 0; i < 64; i++) acc[i] = 0.f;

        #pragma unroll
        for (int p = 0; p < 3; p++) {
            #pragma unroll
            for (int kc = 0; kc < 8; kc++) {
                uint32_t afrag[4];
                uint32_t ab = a_m * 256u + (kc * 16u + a_ks) * 2u;
                ldsm_x4(afrag, abase[p] + SWZ(ab));
                #pragma unroll
                for (int np = 0; np < 8; np++) {
                    uint32_t bfrag[4];
                    uint32_t bb = (kc * 16u + b_ks) * 256u + (np * 16u + b_ns) * 2u;
                    ldsm_x4_t(bfrag, bbase[p] + SWZ(bb));
                    mma16816(&acc[(2 * np) * 4],     afrag, &bfrag[0]);
                    mma16816(&acc[(2 * np + 1) * 4], afrag, &bfrag[2]);
                }
            }
        }

        // epilogue: bias add, store, stats into smem
        int row0 = tile * 128;
        int r0 = row0 + wid * 16 + (lane >> 2);
        int r1 = r0 + 8;
        bool v0 = r0 < M, v1 = r1 < M;
        int cb = (lane & 3) * 2;

        #pragma unroll
        for (int nt = 0; nt < 16; nt++) {
            int c = nt * 8 + cb;
            float b0 = __ldg(&bias[c]);
            float b1 = __ldg(&bias[c + 1]);
            float o00 = acc[nt * 4 + 0] + b0;
            float o01 = acc[nt * 4 + 1] + b1;
            float o10 = acc[nt * 4 + 2] + b0;
            float o11 = acc[nt * 4 + 3] + b1;
            if (v0) *reinterpret_cast<float2*>(&C[(size_t)r0 * 128 + c]) = make_float2(o00, o01);
            if (v1) *reinterpret_cast<float2*>(&C[(size_t)r1 * 128 + c]) = make_float2(o10, o11);

            float s0 = (v0 ? o00 : 0.f) + (v1 ? o10 : 0.f);
            float s1 = (v0 ? o01 : 0.f) + (v1 ? o11 : 0.f);
            float q0 = (v0 ? o00 * o00 : 0.f) + (v1 ? o10 * o10 : 0.f);
            float q1 = (v0 ? o01 * o01 : 0.f) + (v1 ? o11 * o11 : 0.f);
            #pragma unroll
            for (int m = 4; m <= 16; m <<= 1) {
                s0 += __shfl_xor_sync(0xFFFFFFFFu, s0, m);
                s1 += __shfl_xor_sync(0xFFFFFFFFu, s1, m);
                q0 += __shfl_xor_sync(0xFFFFFFFFu, q0, m);
                q1 += __shfl_xor_sync(0xFFFFFFFFu, q1, m);
            }
            if (lane < 4) {
                atomicAdd(&s_stat[c], s0);
                atomicAdd(&s_stat[c + 1], s1);
                atomicAdd(&s_stat[128 + c], q0);
                atomicAdd(&s_stat[128 + c + 1], q1);
            }
        }

        cp_wait0();        // next raw tile landed
        __syncthreads();   // everyone done with hi/lo images
    }

    if (tid < 128) {
        atomicAdd(&g_sum[tid],   s_stat[tid]);
        atomicAdd(&g_sumsq[tid], s_stat[128 + tid]);
    }
}

// ---------------- BN apply + ReLU (+ optional residual) ----------------
__global__ void bn_apply_kernel(const float* __restrict__ z,
                                const float* __restrict__ gamma,
                                const float* __restrict__ beta,
                                const float* __restrict__ res,  // may be null
                                float* __restrict__ out)
{
    const float inv_n = 1.0f / (float)NN;
    int i = blockIdx.x * blockDim.x + threadIdx.x;
    int stride = gridDim.x * blockDim.x;
    const int n4 = NN * (HH / 4);
    for (; i < n4; i += stride) {
        int c0 = (i & 31) * 4;
        float4 zv = reinterpret_cast<const float4*>(z)[i];
        float o[4] = {zv.x, zv.y, zv.z, zv.w};
        #pragma unroll
        for (int j = 0; j < 4; j++) {
            int c = c0 + j;
            float m  = g_sum[c] * inv_n;
            float vr = g_sumsq[c] * inv_n - m * m;
            float rs = rsqrtf(vr + BN_EPS);
            float y = (o[j] - m) * rs * gamma[c] + beta[c];
            o[j] = fmaxf(y, 0.f);
        }
        float4 ov = make_float4(o[0], o[1], o[2], o[3]);
        if (res != nullptr) {
            float4 rv = reinterpret_cast<const float4*>(res)[i];
            ov.x += rv.x; ov.y += rv.y; ov.z += rv.z; ov.w += rv.w;
        }
        reinterpret_cast<float4*>(out)[i] = ov;
    }
}

// ---------------- launch ----------------
extern "C" void kernel_launch(void* const* d_in, const int* in_sizes, int n_in,
                              void* d_out, int out_size)
{
    const float* x      = (const float*)d_in[0];
    const int*   ei     = (const int*)  d_in[1];
    const float* ew     = (const float*)d_in[2];
    const float* fc_w   = (const float*)d_in[3];
    const float* fc_b   = (const float*)d_in[4];
    const float* conv_w = (const float*)d_in[5];
    const float* conv_b = (const float*)d_in[6];
    const float* gamma  = (const float*)d_in[7];
    const float* beta   = (const float*)d_in[8];
    float* out = (float*)d_out;

    const int* row = ei;
    const int* col = ei + EE;

    void *pH, *pZ, *pAGG, *pDegi, *pWhi, *pWlo;
    cudaGetSymbolAddress(&pH, g_H);
    cudaGetSymbolAddress(&pZ, g_Z);
    cudaGetSymbolAddress(&pAGG, g_AGG);
    cudaGetSymbolAddress(&pDegi, g_degi);
    cudaGetSymbolAddress(&pWhi, g_Whi);
    cudaGetSymbolAddress(&pWlo, g_Wlo);
    float* H   = (float*)pH;
    float* Z   = (float*)pZ;
    float* AGG = (float*)pAGG;
    const char* Whi = (const char*)pWhi;
    const char* Wlo = (const char*)pWlo;

    static int smem_set = 0;
    if (!smem_set) {
        cudaFuncSetAttribute(gemm_persist_kernel, cudaFuncAttributeMaxDynamicSharedMemorySize, PS_TOTAL);
        smem_set = 1;
    }

    const int egrid = (EE + 255) / 256;

    // launches 1-3: degree + weight conversion (fc BN stats zeroed inside wconvert)
    zero_int<<<128, 256>>>((int*)pDegi, NN);
    degree_kernel<<<egrid, 256>>>(col);
    wconvert_kernel<<<(3 * 16384 + 255) / 256, 256>>>(fc_w, conv_w);

    // launch 4 (profiled): fc GEMM (persistent)
    gemm_persist_kernel<<<148, 256, PS_TOTAL>>>(x, Whi, Wlo, fc_b, Z, NN);

    // CSR build (independent of the fc GEMM)
    chunk_sums_kernel<<<NCHUNK, CHUNK>>>();
    scan_csum_kernel<<<1, 256>>>();
    scan_offsets_kernel<<<NCHUNK, CHUNK>>>();
    val_scatter_kernel<<<egrid, 256>>>(row, col, ew);

    // fc BN + ReLU
    bn_apply_kernel<<<4096, 256>>>(Z, gamma, beta, nullptr, H);

    for (int l = 0; l < 2; l++) {
        spmm_csr_kernel<<<(NN * 32 + 255) / 256, 256>>>();   // also zeroes BN stats
        gemm_persist_kernel<<<148, 256, PS_TOTAL>>>(AGG, Whi + (size_t)(l + 1) * 32768,
                                                    Wlo + (size_t)(l + 1) * 32768,
                                                    conv_b + l * HH, Z, NN);
        bn_apply_kernel<<<4096, 256>>>(Z, gamma + (l + 1) * HH, beta + (l + 1) * HH,
                                       H, (l == 1) ? out : H);
    }
}

// round 9
// speedup vs baseline: 1.7069x; 1.3773x over previous
#include <cuda_runtime.h>
#include <cuda_fp16.h>
#include <math.h>
#include <stdint.h>

#define NN 100000
#define EE 1600000
#define HH 128
#define BN_EPS 1e-5f
#define CHUNK 512
#define NCHUNK ((NN + CHUNK - 1) / CHUNK)   // 196

// ---------------- device scratch (no allocations allowed) ----------------
__device__ __align__(16) float g_H[NN * HH];     // current hidden state
__device__ __align__(16) float g_Z[NN * HH];     // pre-BN GEMM output
__device__ __align__(16) float g_AGG[NN * HH];   // SpMM output
__device__ __align__(16) int   g_degi[NN];       // in-degree (int)
__device__ __align__(16) int   g_off[NN + 1];    // CSR offsets (by destination)
__device__ __align__(16) int   g_cur[NN];        // scatter cursors
__device__ __align__(16) int2  g_edge[EE];       // CSR: {src, val-bits} per slot
__device__ __align__(16) int   g_csum[NCHUNK];   // chunk sums for scan
__device__ __align__(16) float g_sum[HH];
__device__ __align__(16) float g_sumsq[HH];
// swizzled k-major fp16 weight images (3 weights x 32KB each, hi + lo)
__device__ __align__(16) char g_Whi[3 * 32768];
__device__ __align__(16) char g_Wlo[3 * 32768];

// 256B-row swizzle: XOR 16B-chunk index bits[6:4] with row%8 (bits[10:8])
#define SWZ(b) ((b) ^ ((((b) >> 8) & 7u) << 4))

// gemm smem layout (bytes) — 97KB total -> 2 CTAs/SM
#define GS_A     0            // 32KB fp16 A image
#define GS_BHI   32768        // 32KB
#define GS_BLO   65536        // 32KB
#define GS_STAT  98304        // 256 floats
#define GS_TOTAL (98304 + 1024)

// ---------------- ptx helpers ----------------
__device__ __forceinline__ uint32_t smem_u32(const void* p) {
    uint32_t a;
    asm("{ .reg .u64 t; cvta.to.shared.u64 t, %1; cvt.u32.u64 %0, t; }" : "=r"(a) : "l"(p));
    return a;
}
__device__ __forceinline__ void ldsm_x4(uint32_t* r, uint32_t addr) {
    asm volatile("ldmatrix.sync.aligned.m8n8.x4.shared.b16 {%0,%1,%2,%3}, [%4];"
                 : "=r"(r[0]), "=r"(r[1]), "=r"(r[2]), "=r"(r[3]) : "r"(addr));
}
__device__ __forceinline__ void ldsm_x4_t(uint32_t* r, uint32_t addr) {
    asm volatile("ldmatrix.sync.aligned.m8n8.x4.trans.shared.b16 {%0,%1,%2,%3}, [%4];"
                 : "=r"(r[0]), "=r"(r[1]), "=r"(r[2]), "=r"(r[3]) : "r"(addr));
}
__device__ __forceinline__ void mma16816_f16(float* d, const uint32_t* a, const uint32_t* b) {
    asm volatile("mma.sync.aligned.m16n8k16.row.col.f32.f16.f16.f32 "
                 "{%0,%1,%2,%3}, {%4,%5,%6,%7}, {%8,%9}, {%0,%1,%2,%3};"
                 : "+f"(d[0]), "+f"(d[1]), "+f"(d[2]), "+f"(d[3])
                 : "r"(a[0]), "r"(a[1]), "r"(a[2]), "r"(a[3]), "r"(b[0]), "r"(b[1]));
}
__device__ __forceinline__ void cp_async16(uint32_t dst, const void* src) {
    asm volatile("cp.async.cg.shared.global [%0], [%1], 16;"
                 :: "r"(dst), "l"(src) : "memory");
}
__device__ __forceinline__ void cp_commit() {
    asm volatile("cp.async.commit_group;" ::: "memory");
}
__device__ __forceinline__ void cp_wait0() {
    asm volatile("cp.async.wait_group 0;" ::: "memory");
}

// ---------------- utility kernels ----------------
__global__ void zero_int(int* p, int n) {
    int i = blockIdx.x * blockDim.x + threadIdx.x;
    int stride = gridDim.x * blockDim.x;
    for (; i < n; i += stride) p[i] = 0;
}

__global__ void degree_kernel(const int* __restrict__ col) {
    int e = blockIdx.x * blockDim.x + threadIdx.x;
    if (e < EE) atomicAdd(&g_degi[col[e]], 1);
}

// ---------------- CSR build: two-level exclusive scan ----------------
__global__ void chunk_sums_kernel() {
    __shared__ int sh[CHUNK];
    int t = threadIdx.x;
    int n = blockIdx.x * CHUNK + t;
    sh[t] = (n < NN) ? g_degi[n] : 0;
    __syncthreads();
    for (int s = CHUNK / 2; s > 0; s >>= 1) {
        if (t < s) sh[t] += sh[t + s];
        __syncthreads();
    }
    if (t == 0) g_csum[blockIdx.x] = sh[0];
}

__global__ void scan_csum_kernel() {   // 1 block, 256 threads
    __shared__ int sh[256];
    int t = threadIdx.x;
    int v = (t < NCHUNK) ? g_csum[t] : 0;
    sh[t] = v;
    __syncthreads();
    for (int s = 1; s < 256; s <<= 1) {
        int a = (t >= s) ? sh[t - s] : 0;
        __syncthreads();
        sh[t] += a;
        __syncthreads();
    }
    if (t < NCHUNK) g_csum[t] = sh[t] - v;
}

__global__ void scan_offsets_kernel() {
    __shared__ int sh[CHUNK];
    int t = threadIdx.x;
    int n = blockIdx.x * CHUNK + t;
    int v = (n < NN) ? g_degi[n] : 0;
    sh[t] = v;
    __syncthreads();
    for (int s = 1; s < CHUNK; s <<= 1) {
        int add = (t >= s) ? sh[t - s] : 0;
        __syncthreads();
        sh[t] += add;
        __syncthreads();
    }
    int excl = sh[t] - v + g_csum[blockIdx.x];
    if (n < NN) { g_off[n] = excl; g_cur[n] = excl; }
    if (n == NN - 1) g_off[NN] = excl + v;   // == EE
}

__global__ void val_scatter_kernel(const int* __restrict__ row, const int* __restrict__ col,
                                   const float* __restrict__ w) {
    int e = blockIdx.x * blockDim.x + threadIdx.x;
    if (e < EE) {
        int r = row[e], c = col[e];
        float v = w[e] * rsqrtf((float)g_degi[c]) * rsqrtf((float)g_degi[r]);
        if (!isfinite(v)) v = 0.f;   // nan_to_num
        int p = atomicAdd(&g_cur[c], 1);
        g_edge[p] = make_int2(r, __float_as_int(v));
    }
}

// ---------------- weight conversion: W[k][n] fp32 -> hi/lo fp16 swizzled k-major image ----------------
__global__ void wconvert_kernel(const float* __restrict__ fc_w, const float* __restrict__ conv_w) {
    int idx = blockIdx.x * blockDim.x + threadIdx.x;
    if (blockIdx.x == 0 && threadIdx.x < HH) {
        g_sum[threadIdx.x] = 0.f;
        g_sumsq[threadIdx.x] = 0.f;
    }
    if (idx >= 3 * 16384) return;
    int w   = idx >> 14;
    int rem = idx & 16383;
    int k = rem >> 7;      // input index (row)
    int n = rem & 127;     // output index (col)
    float v = (w == 0) ? fc_w[rem] : conv_w[(w - 1) * 16384 + rem];
    __half hi = __float2half_rn(v);
    __half lo = __float2half_rn(v - __half2float(hi));
    uint32_t byte = (uint32_t)k * 256u + (uint32_t)n * 2u;
    uint32_t sw = SWZ(byte);
    *(__half*)(g_Whi + (size_t)w * 32768 + sw) = hi;
    *(__half*)(g_Wlo + (size_t)w * 32768 + sw) = lo;
}

// ---------------- SpMM (CSR by destination, fp32): one warp per node ----------------
// Block 0 also zeroes the BN stats for the following GEMM.
__global__ __launch_bounds__(256) void spmm_csr_kernel() {
    if (blockIdx.x == 0 && threadIdx.x < HH) {
        g_sum[threadIdx.x] = 0.f;
        g_sumsq[threadIdx.x] = 0.f;
    }
    int warp = (blockIdx.x * blockDim.x + threadIdx.x) >> 5;
    int lane = threadIdx.x & 31;
    if (warp >= NN) return;
    int s = g_off[warp];
    int e = g_off[warp + 1];
    const float4* H4 = reinterpret_cast<const float4*>(g_H);
    float4 acc = make_float4(0.f, 0.f, 0.f, 0.f);
    int k = s;
    for (; k + 1 < e; k += 2) {
        int2 e0 = g_edge[k], e1 = g_edge[k + 1];
        float v0 = __int_as_float(e0.y), v1 = __int_as_float(e1.y);
        float4 a = H4[(size_t)e0.x * 32 + lane];
        float4 b = H4[(size_t)e1.x * 32 + lane];
        acc.x += v0 * a.x + v1 * b.x;
        acc.y += v0 * a.y + v1 * b.y;
        acc.z += v0 * a.z + v1 * b.z;
        acc.w += v0 * a.w + v1 * b.w;
    }
    if (k < e) {
        int2 e0 = g_edge[k];
        float v0 = __int_as_float(e0.y);
        float4 a = H4[(size_t)e0.x * 32 + lane];
        acc.x += v0 * a.x; acc.y += v0 * a.y;
        acc.z += v0 * a.z; acc.w += v0 * a.w;
    }
    reinterpret_cast<float4*>(g_AGG)[(size_t)warp * 32 + lane] = acc;
}

// ---------------- fp16 2-pass mma GEMM: C[M,128] = A[M,128] @ (Whi+Wlo) + bias ----------------
// A quantized to fp16; W exact via hi/lo split. Fused BN-stats epilogue.
// 97KB smem + <=128 regs -> 2 CTAs/SM.
__global__ __launch_bounds__(256, 2) void gemm_f16_kernel(
    const float* __restrict__ A,
    const char* __restrict__ Whi,   // swizzled 32KB fp16 image
    const char* __restrict__ Wlo,
    const float* __restrict__ bias,
    float* __restrict__ C, int M)
{
    extern __shared__ __align__(1024) char smem[];
    uint32_t sb = smem_u32(smem);
    const int tid  = threadIdx.x;
    const int wid  = tid >> 5;
    const int lane = tid & 31;
    const int row0 = blockIdx.x * 128;

    float* s_stat = reinterpret_cast<float*>(smem + GS_STAT);
    s_stat[tid] = 0.f;    // 256 floats: [0:128) sums, [128:256) ssq

    // weights into smem via cp.async (2 x 32KB = 2 x 2048 x 16B)
    #pragma unroll
    for (int i = 0; i < 8; i++) {
        uint32_t off = (uint32_t)(tid + i * 256) * 16u;
        cp_async16(sb + GS_BHI + off, Whi + off);
        cp_async16(sb + GS_BLO + off, Wlo + off);
    }
    cp_commit();

    // A tile: LDG fp32 -> fp16 -> swizzled smem image (overlaps with cp.async)
    {
        const float4* A4 = reinterpret_cast<const float4*>(A);
        #pragma unroll
        for (int i = 0; i < 16; i++) {
            int idx = tid + i * 256;
            int m  = idx >> 5;        // 0..127
            int kg = idx & 31;        // float4 group
            int gr = row0 + m;
            float4 a = (gr < M) ? A4[(size_t)gr * 32 + kg] : make_float4(0.f, 0.f, 0.f, 0.f);
            uint2 u;
            *reinterpret_cast<__half2*>(&u.x) = __floats2half2_rn(a.x, a.y);
            *reinterpret_cast<__half2*>(&u.y) = __floats2half2_rn(a.z, a.w);
            uint32_t sw = SWZ((uint32_t)m * 256u + (uint32_t)kg * 8u);
            *reinterpret_cast<uint2*>(smem + GS_A + sw) = u;
        }
    }
    cp_wait0();
    __syncthreads();

    // per-lane ldmatrix address components
    const uint32_t a_m  = (uint32_t)(wid * 16) + (lane & 7) + ((lane >> 3) & 1) * 8;
    const uint32_t a_ks = (uint32_t)(lane >> 4) * 8;
    const uint32_t b_ks = (uint32_t)(lane & 7) + ((lane >> 3) & 1) * 8;
    const uint32_t b_ns = (uint32_t)((lane >> 4) & 1) * 8;

    float acc[64];
    #pragma unroll
    for (int i = 0; i < 64; i++) acc[i] = 0.f;

    const uint32_t abase = sb + GS_A;
    const uint32_t bbase[2] = { sb + GS_BHI, sb + GS_BLO };

    #pragma unroll
    for (int p = 0; p < 2; p++) {
        #pragma unroll
        for (int kc = 0; kc < 8; kc++) {
            uint32_t afrag[4];
            uint32_t ab = a_m * 256u + (kc * 16u + a_ks) * 2u;
            ldsm_x4(afrag, abase + SWZ(ab));
            #pragma unroll
            for (int np = 0; np < 8; np++) {
                uint32_t bfrag[4];
                uint32_t bb = (kc * 16u + b_ks) * 256u + (np * 16u + b_ns) * 2u;
                ldsm_x4_t(bfrag, bbase[p] + SWZ(bb));
                mma16816_f16(&acc[(2 * np) * 4],     afrag, &bfrag[0]);
                mma16816_f16(&acc[(2 * np + 1) * 4], afrag, &bfrag[2]);
            }
        }
    }

    // epilogue: bias add, store, fused BN stats
    int r0 = row0 + wid * 16 + (lane >> 2);
    int r1 = r0 + 8;
    bool v0 = r0 < M, v1 = r1 < M;
    int cb = (lane & 3) * 2;

    #pragma unroll
    for (int nt = 0; nt < 16; nt++) {
        int c = nt * 8 + cb;
        float b0 = __ldg(&bias[c]);
        float b1 = __ldg(&bias[c + 1]);
        float o00 = acc[nt * 4 + 0] + b0;
        float o01 = acc[nt * 4 + 1] + b1;
        float o10 = acc[nt * 4 + 2] + b0;
        float o11 = acc[nt * 4 + 3] + b1;
        if (v0) *reinterpret_cast<float2*>(&C[(size_t)r0 * 128 + c]) = make_float2(o00, o01);
        if (v1) *reinterpret_cast<float2*>(&C[(size_t)r1 * 128 + c]) = make_float2(o10, o11);

        float s0 = (v0 ? o00 : 0.f) + (v1 ? o10 : 0.f);
        float s1 = (v0 ? o01 : 0.f) + (v1 ? o11 : 0.f);
        float q0 = (v0 ? o00 * o00 : 0.f) + (v1 ? o10 * o10 : 0.f);
        float q1 = (v0 ? o01 * o01 : 0.f) + (v1 ? o11 * o11 : 0.f);
        #pragma unroll
        for (int m = 4; m <= 16; m <<= 1) {
            s0 += __shfl_xor_sync(0xFFFFFFFFu, s0, m);
            s1 += __shfl_xor_sync(0xFFFFFFFFu, s1, m);
            q0 += __shfl_xor_sync(0xFFFFFFFFu, q0, m);
            q1 += __shfl_xor_sync(0xFFFFFFFFu, q1, m);
        }
        if (lane < 4) {
            atomicAdd(&s_stat[c], s0);
            atomicAdd(&s_stat[c + 1], s1);
            atomicAdd(&s_stat[128 + c], q0);
            atomicAdd(&s_stat[128 + c + 1], q1);
        }
    }
    __syncthreads();
    if (tid < 128) {
        atomicAdd(&g_sum[tid],   s_stat[tid]);
        atomicAdd(&g_sumsq[tid], s_stat[128 + tid]);
    }
}

// ---------------- BN apply + ReLU (+ optional residual) ----------------
__global__ void bn_apply_kernel(const float* __restrict__ z,
                                const float* __restrict__ gamma,
                                const float* __restrict__ beta,
                                const float* __restrict__ res,  // may be null
                                float* __restrict__ out)
{
    const float inv_n = 1.0f / (float)NN;
    int i = blockIdx.x * blockDim.x + threadIdx.x;
    int stride = gridDim.x * blockDim.x;
    const int n4 = NN * (HH / 4);
    for (; i < n4; i += stride) {
        int c0 = (i & 31) * 4;
        float4 zv = reinterpret_cast<const float4*>(z)[i];
        float o[4] = {zv.x, zv.y, zv.z, zv.w};
        #pragma unroll
        for (int j = 0; j < 4; j++) {
            int c = c0 + j;
            float m  = g_sum[c] * inv_n;
            float vr = g_sumsq[c] * inv_n - m * m;
            float rs = rsqrtf(vr + BN_EPS);
            float y = (o[j] - m) * rs * gamma[c] + beta[c];
            o[j] = fmaxf(y, 0.f);
        }
        float4 ov = make_float4(o[0], o[1], o[2], o[3]);
        if (res != nullptr) {
            float4 rv = reinterpret_cast<const float4*>(res)[i];
            ov.x += rv.x; ov.y += rv.y; ov.z += rv.z; ov.w += rv.w;
        }
        reinterpret_cast<float4*>(out)[i] = ov;
    }
}

// ---------------- launch ----------------
extern "C" void kernel_launch(void* const* d_in, const int* in_sizes, int n_in,
                              void* d_out, int out_size)
{
    const float* x      = (const float*)d_in[0];
    const int*   ei     = (const int*)  d_in[1];
    const float* ew     = (const float*)d_in[2];
    const float* fc_w   = (const float*)d_in[3];
    const float* fc_b   = (const float*)d_in[4];
    const float* conv_w = (const float*)d_in[5];
    const float* conv_b = (const float*)d_in[6];
    const float* gamma  = (const float*)d_in[7];
    const float* beta   = (const float*)d_in[8];
    float* out = (float*)d_out;

    const int* row = ei;
    const int* col = ei + EE;

    void *pH, *pZ, *pAGG, *pDegi, *pWhi, *pWlo;
    cudaGetSymbolAddress(&pH, g_H);
    cudaGetSymbolAddress(&pZ, g_Z);
    cudaGetSymbolAddress(&pAGG, g_AGG);
    cudaGetSymbolAddress(&pDegi, g_degi);
    cudaGetSymbolAddress(&pWhi, g_Whi);
    cudaGetSymbolAddress(&pWlo, g_Wlo);
    float* H   = (float*)pH;
    float* Z   = (float*)pZ;
    float* AGG = (float*)pAGG;
    const char* Whi = (const char*)pWhi;
    const char* Wlo = (const char*)pWlo;

    static int smem_set = 0;
    if (!smem_set) {
        cudaFuncSetAttribute(gemm_f16_kernel, cudaFuncAttributeMaxDynamicSharedMemorySize, GS_TOTAL);
        smem_set = 1;
    }

    const int egrid = (EE + 255) / 256;
    const int ggrid = (NN + 127) / 128;   // 782

    // launches 1-3: degree + weight conversion (fc BN stats zeroed inside wconvert)
    zero_int<<<128, 256>>>((int*)pDegi, NN);
    degree_kernel<<<egrid, 256>>>(col);
    wconvert_kernel<<<(3 * 16384 + 255) / 256, 256>>>(fc_w, conv_w);

    // launch 4 (profiled): fc GEMM
    gemm_f16_kernel<<<ggrid, 256, GS_TOTAL>>>(x, Whi, Wlo, fc_b, Z, NN);

    // CSR build (independent of the fc GEMM)
    chunk_sums_kernel<<<NCHUNK, CHUNK>>>();
    scan_csum_kernel<<<1, 256>>>();
    scan_offsets_kernel<<<NCHUNK, CHUNK>>>();
    val_scatter_kernel<<<egrid, 256>>>(row, col, ew);

    // fc BN + ReLU
    bn_apply_kernel<<<4096, 256>>>(Z, gamma, beta, nullptr, H);

    for (int l = 0; l < 2; l++) {
        spmm_csr_kernel<<<(NN * 32 + 255) / 256, 256>>>();   // also zeroes BN stats
        gemm_f16_kernel<<<ggrid, 256, GS_TOTAL>>>(AGG, Whi + (size_t)(l + 1) * 32768,
                                                  Wlo + (size_t)(l + 1) * 32768,
                                                  conv_b + l * HH, Z, NN);
        bn_apply_kernel<<<4096, 256>>>(Z, gamma + (l + 1) * HH, beta + (l + 1) * HH,
                                       H, (l == 1) ? out : H);
    }
}

// round 10
// speedup vs baseline: 1.7378x; 1.0182x over previous
#include <cuda_runtime.h>
#include <cuda_fp16.h>
#include <math.h>
#include <stdint.h>

#define NN 100000
#define EE 1600000
#define HH 128
#define BN_EPS 1e-5f
#define CHUNK 512
#define NCHUNK ((NN + CHUNK - 1) / CHUNK)   // 196
#define NT ((NN + 127) / 128)               // 782 tiles

// ---------------- device scratch (no allocations allowed) ----------------
__device__ __align__(16) float g_H[NN * HH];     // current hidden state (fp32, residual)
__device__ __align__(16) float g_Z[NN * HH];     // pre-BN GEMM output
__device__ __align__(16) char  g_A16[NT * 32768];// swizzled fp16 tile image of AGG (SpMM out)
__device__ __align__(16) char  g_X16[NT * 32768];// swizzled fp16 tile image of x
__device__ __align__(16) int   g_degi[NN];       // in-degree (int)
__device__ __align__(16) int   g_off[NN + 1];    // CSR offsets (by destination)
__device__ __align__(16) int   g_cur[NN];        // scatter cursors
__device__ __align__(16) int2  g_edge[EE];       // CSR: {src, val-bits} per slot
__device__ __align__(16) int   g_csum[NCHUNK];   // chunk sums for scan
__device__ __align__(16) float g_sum[HH];
__device__ __align__(16) float g_sumsq[HH];
// swizzled k-major fp16 weight images (3 weights x 32KB each, hi + lo)
__device__ __align__(16) char g_Whi[3 * 32768];
__device__ __align__(16) char g_Wlo[3 * 32768];

// 256B-row swizzle: XOR 16B-chunk index bits[6:4] with row%8 (bits[10:8])
#define SWZ(b) ((b) ^ ((((b) >> 8) & 7u) << 4))

// gemm smem layout (bytes) — 97KB total -> 2 CTAs/SM
#define GS_A     0            // 32KB fp16 A image
#define GS_BHI   32768        // 32KB
#define GS_BLO   65536        // 32KB
#define GS_STAT  98304        // 256 floats
#define GS_TOTAL (98304 + 1024)

// ---------------- ptx helpers ----------------
__device__ __forceinline__ uint32_t smem_u32(const void* p) {
    uint32_t a;
    asm("{ .reg .u64 t; cvta.to.shared.u64 t, %1; cvt.u32.u64 %0, t; }" : "=r"(a) : "l"(p));
    return a;
}
__device__ __forceinline__ void ldsm_x4(uint32_t* r, uint32_t addr) {
    asm volatile("ldmatrix.sync.aligned.m8n8.x4.shared.b16 {%0,%1,%2,%3}, [%4];"
                 : "=r"(r[0]), "=r"(r[1]), "=r"(r[2]), "=r"(r[3]) : "r"(addr));
}
__device__ __forceinline__ void ldsm_x4_t(uint32_t* r, uint32_t addr) {
    asm volatile("ldmatrix.sync.aligned.m8n8.x4.trans.shared.b16 {%0,%1,%2,%3}, [%4];"
                 : "=r"(r[0]), "=r"(r[1]), "=r"(r[2]), "=r"(r[3]) : "r"(addr));
}
__device__ __forceinline__ void mma16816_f16(float* d, const uint32_t* a, const uint32_t* b) {
    asm volatile("mma.sync.aligned.m16n8k16.row.col.f32.f16.f16.f32 "
                 "{%0,%1,%2,%3}, {%4,%5,%6,%7}, {%8,%9}, {%0,%1,%2,%3};"
                 : "+f"(d[0]), "+f"(d[1]), "+f"(d[2]), "+f"(d[3])
                 : "r"(a[0]), "r"(a[1]), "r"(a[2]), "r"(a[3]), "r"(b[0]), "r"(b[1]));
}
__device__ __forceinline__ void cp_async16(uint32_t dst, const void* src) {
    asm volatile("cp.async.cg.shared.global [%0], [%1], 16;"
                 :: "r"(dst), "l"(src) : "memory");
}
__device__ __forceinline__ void cp_commit() {
    asm volatile("cp.async.commit_group;" ::: "memory");
}
__device__ __forceinline__ void cp_wait0() {
    asm volatile("cp.async.wait_group 0;" ::: "memory");
}

// ---------------- zx: zero degi + convert x -> swizzled fp16 tile image ----------------
__global__ void zx_kernel(const float* __restrict__ x) {
    int stride = gridDim.x * blockDim.x;
    int t0 = blockIdx.x * blockDim.x + threadIdx.x;
    for (int i = t0; i < NN; i += stride) g_degi[i] = 0;
    const float4* x4 = reinterpret_cast<const float4*>(x);
    const int total = NT * 4096;            // uint2 (8B) items per tile: 128*32
    for (int idx = t0; idx < total; idx += stride) {
        int r  = idx >> 5;
        int kg = idx & 31;
        float4 a = (r < NN) ? x4[(size_t)r * 32 + kg] : make_float4(0.f, 0.f, 0.f, 0.f);
        uint2 u;
        *reinterpret_cast<__half2*>(&u.x) = __floats2half2_rn(a.x, a.y);
        *reinterpret_cast<__half2*>(&u.y) = __floats2half2_rn(a.z, a.w);
        uint32_t dst = (uint32_t)(r >> 7) * 32768u
                     + SWZ((uint32_t)(r & 127) * 256u + (uint32_t)kg * 8u);
        *reinterpret_cast<uint2*>(g_X16 + dst) = u;
    }
}

__global__ void degree_kernel(const int* __restrict__ col) {
    int e = blockIdx.x * blockDim.x + threadIdx.x;
    if (e < EE) atomicAdd(&g_degi[col[e]], 1);
}

// ---------------- CSR build: two-level exclusive scan ----------------
__global__ void chunk_sums_kernel() {
    __shared__ int sh[CHUNK];
    int t = threadIdx.x;
    int n = blockIdx.x * CHUNK + t;
    sh[t] = (n < NN) ? g_degi[n] : 0;
    __syncthreads();
    for (int s = CHUNK / 2; s > 0; s >>= 1) {
        if (t < s) sh[t] += sh[t + s];
        __syncthreads();
    }
    if (t == 0) g_csum[blockIdx.x] = sh[0];
}

__global__ void scan_csum_kernel() {   // 1 block, 256 threads
    __shared__ int sh[256];
    int t = threadIdx.x;
    int v = (t < NCHUNK) ? g_csum[t] : 0;
    sh[t] = v;
    __syncthreads();
    for (int s = 1; s < 256; s <<= 1) {
        int a = (t >= s) ? sh[t - s] : 0;
        __syncthreads();
        sh[t] += a;
        __syncthreads();
    }
    if (t < NCHUNK) g_csum[t] = sh[t] - v;
}

__global__ void scan_offsets_kernel() {
    __shared__ int sh[CHUNK];
    int t = threadIdx.x;
    int n = blockIdx.x * CHUNK + t;
    int v = (n < NN) ? g_degi[n] : 0;
    sh[t] = v;
    __syncthreads();
    for (int s = 1; s < CHUNK; s <<= 1) {
        int add = (t >= s) ? sh[t - s] : 0;
        __syncthreads();
        sh[t] += add;
        __syncthreads();
    }
    int excl = sh[t] - v + g_csum[blockIdx.x];
    if (n < NN) { g_off[n] = excl; g_cur[n] = excl; }
    if (n == NN - 1) g_off[NN] = excl + v;   // == EE
}

__global__ void val_scatter_kernel(const int* __restrict__ row, const int* __restrict__ col,
                                   const float* __restrict__ w) {
    int e = blockIdx.x * blockDim.x + threadIdx.x;
    if (e < EE) {
        int r = row[e], c = col[e];
        float v = w[e] * rsqrtf((float)g_degi[c]) * rsqrtf((float)g_degi[r]);
        if (!isfinite(v)) v = 0.f;   // nan_to_num
        int p = atomicAdd(&g_cur[c], 1);
        g_edge[p] = make_int2(r, __float_as_int(v));
    }
}

// ---------------- weight conversion: W[k][n] fp32 -> hi/lo fp16 swizzled k-major image ----------------
__global__ void wconvert_kernel(const float* __restrict__ fc_w, const float* __restrict__ conv_w) {
    int idx = blockIdx.x * blockDim.x + threadIdx.x;
    if (blockIdx.x == 0 && threadIdx.x < HH) {
        g_sum[threadIdx.x] = 0.f;
        g_sumsq[threadIdx.x] = 0.f;
    }
    if (idx >= 3 * 16384) return;
    int w   = idx >> 14;
    int rem = idx & 16383;
    int k = rem >> 7;      // input index (row)
    int n = rem & 127;     // output index (col)
    float v = (w == 0) ? fc_w[rem] : conv_w[(w - 1) * 16384 + rem];
    __half hi = __float2half_rn(v);
    __half lo = __float2half_rn(v - __half2float(hi));
    uint32_t byte = (uint32_t)k * 256u + (uint32_t)n * 2u;
    uint32_t sw = SWZ(byte);
    *(__half*)(g_Whi + (size_t)w * 32768 + sw) = hi;
    *(__half*)(g_Wlo + (size_t)w * 32768 + sw) = lo;
}

// ---------------- SpMM (CSR by destination, fp32 gathers): one warp per node ----------------
// Writes the result directly as swizzled fp16 tile image (GEMM A input).
// Block 0 also zeroes the BN stats for the following GEMM.
__global__ __launch_bounds__(256) void spmm_csr_kernel() {
    if (blockIdx.x == 0 && threadIdx.x < HH) {
        g_sum[threadIdx.x] = 0.f;
        g_sumsq[threadIdx.x] = 0.f;
    }
    int warp = (blockIdx.x * blockDim.x + threadIdx.x) >> 5;
    int lane = threadIdx.x & 31;
    if (warp >= NN) return;
    int s = g_off[warp];
    int e = g_off[warp + 1];
    const float4* H4 = reinterpret_cast<const float4*>(g_H);
    float4 acc = make_float4(0.f, 0.f, 0.f, 0.f);
    int k = s;
    for (; k + 1 < e; k += 2) {
        int2 e0 = g_edge[k], e1 = g_edge[k + 1];
        float v0 = __int_as_float(e0.y), v1 = __int_as_float(e1.y);
        float4 a = H4[(size_t)e0.x * 32 + lane];
        float4 b = H4[(size_t)e1.x * 32 + lane];
        acc.x += v0 * a.x + v1 * b.x;
        acc.y += v0 * a.y + v1 * b.y;
        acc.z += v0 * a.z + v1 * b.z;
        acc.w += v0 * a.w + v1 * b.w;
    }
    if (k < e) {
        int2 e0 = g_edge[k];
        float v0 = __int_as_float(e0.y);
        float4 a = H4[(size_t)e0.x * 32 + lane];
        acc.x += v0 * a.x; acc.y += v0 * a.y;
        acc.z += v0 * a.z; acc.w += v0 * a.w;
    }
    // store as fp16 into the swizzled tile image (same quantization point the GEMM used)
    uint2 u;
    *reinterpret_cast<__half2*>(&u.x) = __floats2half2_rn(acc.x, acc.y);
    *reinterpret_cast<__half2*>(&u.y) = __floats2half2_rn(acc.z, acc.w);
    uint32_t dst = (uint32_t)(warp >> 7) * 32768u
                 + SWZ((uint32_t)(warp & 127) * 256u + (uint32_t)lane * 8u);
    *reinterpret_cast<uint2*>(g_A16 + dst) = u;
}

// ---------------- fp16 2-pass mma GEMM, pure-cp.async front end ----------------
// A16: pre-swizzled fp16 tile image. W exact via hi/lo split. Fused BN-stats epilogue.
__global__ __launch_bounds__(256, 2) void gemm_f16s_kernel(
    const char* __restrict__ A16,
    const char* __restrict__ Whi,
    const char* __restrict__ Wlo,
    const float* __restrict__ bias,
    float* __restrict__ C, int M)
{
    extern __shared__ __align__(1024) char smem[];
    uint32_t sb = smem_u32(smem);
    const int tid  = threadIdx.x;
    const int wid  = tid >> 5;
    const int lane = tid & 31;
    const int row0 = blockIdx.x * 128;

    float* s_stat = reinterpret_cast<float*>(smem + GS_STAT);
    s_stat[tid] = 0.f;    // 256 floats: [0:128) sums, [128:256) ssq

    // A image + both weight images via cp.async (3 x 32KB = 3 x 2048 x 16B)
    const char* Atile = A16 + (size_t)blockIdx.x * 32768;
    #pragma unroll
    for (int i = 0; i < 8; i++) {
        uint32_t off = (uint32_t)(tid + i * 256) * 16u;
        cp_async16(sb + GS_A + off, Atile + off);
        cp_async16(sb + GS_BHI + off, Whi + off);
        cp_async16(sb + GS_BLO + off, Wlo + off);
    }
    cp_commit();
    cp_wait0();
    __syncthreads();

    // per-lane ldmatrix address components
    const uint32_t a_m  = (uint32_t)(wid * 16) + (lane & 7) + ((lane >> 3) & 1) * 8;
    const uint32_t a_ks = (uint32_t)(lane >> 4) * 8;
    const uint32_t b_ks = (uint32_t)(lane & 7) + ((lane >> 3) & 1) * 8;
    const uint32_t b_ns = (uint32_t)((lane >> 4) & 1) * 8;

    float acc[64];
    #pragma unroll
    for (int i = 0; i < 64; i++) acc[i] = 0.f;

    const uint32_t abase = sb + GS_A;
    const uint32_t bbase[2] = { sb + GS_BHI, sb + GS_BLO };

    #pragma unroll
    for (int p = 0; p < 2; p++) {
        #pragma unroll
        for (int kc = 0; kc < 8; kc++) {
            uint32_t afrag[4];
            uint32_t ab = a_m * 256u + (kc * 16u + a_ks) * 2u;
            ldsm_x4(afrag, abase + SWZ(ab));
            #pragma unroll
            for (int np = 0; np < 8; np++) {
                uint32_t bfrag[4];
                uint32_t bb = (kc * 16u + b_ks) * 256u + (np * 16u + b_ns) * 2u;
                ldsm_x4_t(bfrag, bbase[p] + SWZ(bb));
                mma16816_f16(&acc[(2 * np) * 4],     afrag, &bfrag[0]);
                mma16816_f16(&acc[(2 * np + 1) * 4], afrag, &bfrag[2]);
            }
        }
    }

    // epilogue: bias add, store, fused BN stats
    int r0 = row0 + wid * 16 + (lane >> 2);
    int r1 = r0 + 8;
    bool v0 = r0 < M, v1 = r1 < M;
    int cb = (lane & 3) * 2;

    #pragma unroll
    for (int nt = 0; nt < 16; nt++) {
        int c = nt * 8 + cb;
        float b0 = __ldg(&bias[c]);
        float b1 = __ldg(&bias[c + 1]);
        float o00 = acc[nt * 4 + 0] + b0;
        float o01 = acc[nt * 4 + 1] + b1;
        float o10 = acc[nt * 4 + 2] + b0;
        float o11 = acc[nt * 4 + 3] + b1;
        if (v0) *reinterpret_cast<float2*>(&C[(size_t)r0 * 128 + c]) = make_float2(o00, o01);
        if (v1) *reinterpret_cast<float2*>(&C[(size_t)r1 * 128 + c]) = make_float2(o10, o11);

        float s0 = (v0 ? o00 : 0.f) + (v1 ? o10 : 0.f);
        float s1 = (v0 ? o01 : 0.f) + (v1 ? o11 : 0.f);
        float q0 = (v0 ? o00 * o00 : 0.f) + (v1 ? o10 * o10 : 0.f);
        float q1 = (v0 ? o01 * o01 : 0.f) + (v1 ? o11 * o11 : 0.f);
        #pragma unroll
        for (int m = 4; m <= 16; m <<= 1) {
            s0 += __shfl_xor_sync(0xFFFFFFFFu, s0, m);
            s1 += __shfl_xor_sync(0xFFFFFFFFu, s1, m);
            q0 += __shfl_xor_sync(0xFFFFFFFFu, q0, m);
            q1 += __shfl_xor_sync(0xFFFFFFFFu, q1, m);
        }
        if (lane < 4) {
            atomicAdd(&s_stat[c], s0);
            atomicAdd(&s_stat[c + 1], s1);
            atomicAdd(&s_stat[128 + c], q0);
            atomicAdd(&s_stat[128 + c + 1], q1);
        }
    }
    __syncthreads();
    if (tid < 128) {
        atomicAdd(&g_sum[tid],   s_stat[tid]);
        atomicAdd(&g_sumsq[tid], s_stat[128 + tid]);
    }
}

// ---------------- BN apply + ReLU (+ optional residual) ----------------
__global__ void bn_apply_kernel(const float* __restrict__ z,
                                const float* __restrict__ gamma,
                                const float* __restrict__ beta,
                                const float* __restrict__ res,  // may be null
                                float* __restrict__ out)
{
    const float inv_n = 1.0f / (float)NN;
    int i = blockIdx.x * blockDim.x + threadIdx.x;
    int stride = gridDim.x * blockDim.x;
    const int n4 = NN * (HH / 4);
    for (; i < n4; i += stride) {
        int c0 = (i & 31) * 4;
        float4 zv = reinterpret_cast<const float4*>(z)[i];
        float o[4] = {zv.x, zv.y, zv.z, zv.w};
        #pragma unroll
        for (int j = 0; j < 4; j++) {
            int c = c0 + j;
            float m  = g_sum[c] * inv_n;
            float vr = g_sumsq[c] * inv_n - m * m;
            float rs = rsqrtf(vr + BN_EPS);
            float y = (o[j] - m) * rs * gamma[c] + beta[c];
            o[j] = fmaxf(y, 0.f);
        }
        float4 ov = make_float4(o[0], o[1], o[2], o[3]);
        if (res != nullptr) {
            float4 rv = reinterpret_cast<const float4*>(res)[i];
            ov.x += rv.x; ov.y += rv.y; ov.z += rv.z; ov.w += rv.w;
        }
        reinterpret_cast<float4*>(out)[i] = ov;
    }
}

// ---------------- launch ----------------
extern "C" void kernel_launch(void* const* d_in, const int* in_sizes, int n_in,
                              void* d_out, int out_size)
{
    const float* x      = (const float*)d_in[0];
    const int*   ei     = (const int*)  d_in[1];
    const float* ew     = (const float*)d_in[2];
    const float* fc_w   = (const float*)d_in[3];
    const float* fc_b   = (const float*)d_in[4];
    const float* conv_w = (const float*)d_in[5];
    const float* conv_b = (const float*)d_in[6];
    const float* gamma  = (const float*)d_in[7];
    const float* beta   = (const float*)d_in[8];
    float* out = (float*)d_out;

    const int* row = ei;
    const int* col = ei + EE;

    void *pH, *pZ, *pA16, *pX16, *pWhi, *pWlo;
    cudaGetSymbolAddress(&pH, g_H);
    cudaGetSymbolAddress(&pZ, g_Z);
    cudaGetSymbolAddress(&pA16, g_A16);
    cudaGetSymbolAddress(&pX16, g_X16);
    cudaGetSymbolAddress(&pWhi, g_Whi);
    cudaGetSymbolAddress(&pWlo, g_Wlo);
    float* H   = (float*)pH;
    float* Z   = (float*)pZ;
    const char* A16 = (const char*)pA16;
    const char* X16 = (const char*)pX16;
    const char* Whi = (const char*)pWhi;
    const char* Wlo = (const char*)pWlo;

    static int smem_set = 0;
    if (!smem_set) {
        cudaFuncSetAttribute(gemm_f16s_kernel, cudaFuncAttributeMaxDynamicSharedMemorySize, GS_TOTAL);
        smem_set = 1;
    }

    const int egrid = (EE + 255) / 256;

    // launches 1-3: zero degi + x conversion, degree, weight conversion (+stat zero)
    zx_kernel<<<2048, 256>>>(x);
    degree_kernel<<<egrid, 256>>>(col);
    wconvert_kernel<<<(3 * 16384 + 255) / 256, 256>>>(fc_w, conv_w);

    // launch 4 (profiled): fc GEMM from pre-converted X16
    gemm_f16s_kernel<<<NT, 256, GS_TOTAL>>>(X16, Whi, Wlo, fc_b, Z, NN);

    // CSR build (independent of the fc GEMM)
    chunk_sums_kernel<<<NCHUNK, CHUNK>>>();
    scan_csum_kernel<<<1, 256>>>();
    scan_offsets_kernel<<<NCHUNK, CHUNK>>>();
    val_scatter_kernel<<<egrid, 256>>>(row, col, ew);

    // fc BN + ReLU
    bn_apply_kernel<<<4096, 256>>>(Z, gamma, beta, nullptr, H);

    for (int l = 0; l < 2; l++) {
        spmm_csr_kernel<<<(NN * 32 + 255) / 256, 256>>>();   // writes g_A16, zeroes BN stats
        gemm_f16s_kernel<<<NT, 256, GS_TOTAL>>>(A16, Whi + (size_t)(l + 1) * 32768,
                                                Wlo + (size_t)(l + 1) * 32768,
                                                conv_b + l * HH, Z, NN);
        bn_apply_kernel<<<4096, 256>>>(Z, gamma + (l + 1) * HH, beta + (l + 1) * HH,
                                       H, (l == 1) ? out : H);
    }
}